// round 2
// baseline (speedup 1.0000x reference)
#include <cuda_runtime.h>
#include <math_constants.h>

// CollectNeighbourAverageAndMax: V=100000, K=32, F=64
// out[v, 0:64]   = sum_k x[idxs[v,k], :] / K
// out[v, 64:128] = max_k x[idxs[v,k], :]
//
// Half-warp per vertex, float4 per lane:
//   lanes 0-15  -> vertex vA = 2*warp_id,   lane hl owns features [4hl, 4hl+3]
//   lanes 16-31 -> vertex vB = 2*warp_id+1, same feature mapping
// Per iteration k, ONE LDG.128 fetches the full 256B row of x[idx_k] for BOTH
// vertices (2x256B = 4 wavefronts). Index pairs loaded as int2 (64 ints/warp,
// coalesced) and broadcast with a single computed-source shfl per k.
// Gather loads are explicitly batched 8-deep to force MLP against L2 latency.

static constexpr int V = 100000;
static constexpr int K = 32;
static constexpr int F = 64;

__global__ __launch_bounds__(256) void collect_nb_kernel(
    const float* __restrict__ x,
    const int* __restrict__ idxs,
    float* __restrict__ out)
{
    const int warp_id = (blockIdx.x * blockDim.x + threadIdx.x) >> 5;
    const int lane = threadIdx.x & 31;
    const int vA = warp_id * 2;
    if (vA >= V) return;

    const int half = lane & 16;   // 0 for vertex A half, 16 for vertex B half
    const int hl   = lane & 15;   // lane within half-warp

    // 64 neighbor indices (vA's 32 then vB's 32) are contiguous.
    // Lane l holds elements {2l, 2l+1} as int2.
    const int2 myidx = *reinterpret_cast<const int2*>(idxs + (size_t)vA * K + 2 * lane);

    float4 s = make_float4(0.f, 0.f, 0.f, 0.f);
    float4 m = make_float4(-CUDART_INF_F, -CUDART_INF_F, -CUDART_INF_F, -CUDART_INF_F);

    const float* xb = x + 4 * hl;   // this lane's feature offset within a row

    #pragma unroll
    for (int k0 = 0; k0 < K; k0 += 8) {
        float4 r[8];
        // Batch of 8 independent gathers -> 8 LDG.128 in flight per warp.
        #pragma unroll
        for (int j = 0; j < 8; ++j) {
            const int k = k0 + j;
            // Element k (low half needs vA's k -> flat index k, lanes 0..15;
            // high half needs vB's k -> flat index 32+k, lanes 16..31).
            // Flat element e lives in lane e/2, component e%2.
            const int src = (k >> 1) + half;
            const int nb = __shfl_sync(0xffffffffu,
                                       (k & 1) ? myidx.y : myidx.x, src);
            r[j] = *reinterpret_cast<const float4*>(xb + (size_t)nb * F);
        }
        #pragma unroll
        for (int j = 0; j < 8; ++j) {
            s.x += r[j].x; s.y += r[j].y; s.z += r[j].z; s.w += r[j].w;
            m.x = fmaxf(m.x, r[j].x); m.y = fmaxf(m.y, r[j].y);
            m.z = fmaxf(m.z, r[j].z); m.w = fmaxf(m.w, r[j].w);
        }
    }

    constexpr float inv_k = 1.0f / K;
    s.x *= inv_k; s.y *= inv_k; s.z *= inv_k; s.w *= inv_k;

    // Output rows for vA and vB are contiguous: vA at +0, vB at +128 floats.
    float* orow = out + (size_t)vA * (2 * F) + (half ? (2 * F) : 0);
    *reinterpret_cast<float4*>(orow + 4 * hl) = s;        // mean part
    *reinterpret_cast<float4*>(orow + F + 4 * hl) = m;    // max part
}

extern "C" void kernel_launch(void* const* d_in, const int* in_sizes, int n_in,
                              void* d_out, int out_size)
{
    const float* x = (const float*)d_in[0];
    const int* idxs = (const int*)d_in[1];
    float* out = (float*)d_out;

    const int threads = 256;                      // 8 warps -> 16 vertices/block
    const int verts_per_block = (threads / 32) * 2;
    const int blocks = (V + verts_per_block - 1) / verts_per_block;  // 6250

    collect_nb_kernel<<<blocks, threads>>>(x, idxs, out);
}

// round 3
// speedup vs baseline: 1.0779x; 1.0779x over previous
#include <cuda_runtime.h>
#include <math_constants.h>

// CollectNeighbourAverageAndMax: V=100000, K=32, F=64
// out[v, 0:64]   = sum_k x[idxs[v,k], :] / K
// out[v, 64:128] = max_k x[idxs[v,k], :]
//
// Warp per vertex (R1 winner), lane l owns features [2l, 2l+1] as float2.
// R3 change: force MLP=8 — explicit 8-deep gather batches into a register
// array, shfl'ing PRE-MULTIPLIED row offsets so each load is one IMAD+LDG.64.
// Keeps regs <= 64 so full 32-warp/SM occupancy is preserved.

static constexpr int V = 100000;
static constexpr int K = 32;
static constexpr int F = 64;

__global__ __launch_bounds__(256) void collect_nb_kernel(
    const float* __restrict__ x,
    const int* __restrict__ idxs,
    float* __restrict__ out)
{
    const int warp_id = (blockIdx.x * blockDim.x + threadIdx.x) >> 5;
    const int lane = threadIdx.x & 31;
    if (warp_id >= V) return;

    // Coalesced index load: lane k holds idxs[v*K + k].
    // Pre-multiply to a row offset so post-shfl address math is one IADD/LEA.
    const int my_row = idxs[warp_id * K + lane] * F;

    float2 s = make_float2(0.0f, 0.0f);
    float2 m = make_float2(-CUDART_INF_F, -CUDART_INF_F);

    const float* xb = x + 2 * lane;  // this lane's feature offset within a row

    #pragma unroll
    for (int k0 = 0; k0 < K; k0 += 8) {
        // Phase 1: 8 independent shfls (all depend only on my_row).
        int row[8];
        #pragma unroll
        for (int j = 0; j < 8; ++j)
            row[j] = __shfl_sync(0xffffffffu, my_row, k0 + j);

        // Phase 2: 8 independent LDG.64s in flight.
        float2 r[8];
        #pragma unroll
        for (int j = 0; j < 8; ++j)
            r[j] = *reinterpret_cast<const float2*>(xb + row[j]);

        // Phase 3: reduce.
        #pragma unroll
        for (int j = 0; j < 8; ++j) {
            s.x += r[j].x;
            s.y += r[j].y;
            m.x = fmaxf(m.x, r[j].x);
            m.y = fmaxf(m.y, r[j].y);
        }
    }

    constexpr float inv_k = 1.0f / K;
    s.x *= inv_k;
    s.y *= inv_k;

    float* o = out + (size_t)warp_id * (2 * F);
    *reinterpret_cast<float2*>(o + 2 * lane) = s;       // mean part
    *reinterpret_cast<float2*>(o + F + 2 * lane) = m;   // max part
}

extern "C" void kernel_launch(void* const* d_in, const int* in_sizes, int n_in,
                              void* d_out, int out_size)
{
    const float* x = (const float*)d_in[0];
    const int* idxs = (const int*)d_in[1];
    float* out = (float*)d_out;

    const int threads = 256;                  // 8 warps -> 8 vertices per block
    const int warps_per_block = threads / 32;
    const int blocks = (V + warps_per_block - 1) / warps_per_block;  // 12500

    collect_nb_kernel<<<blocks, threads>>>(x, idxs, out);
}